// round 17
// baseline (speedup 1.0000x reference)
#include <cuda_runtime.h>
#include <math.h>

#define NB 64          // batch
#define SEQ 64         // seq len
#define MD 256         // model dim
#define HF 128         // half
#define WD 300         // word dim
#define MLPD 1024
#define NC 3
#define BKT 16         // K tile
#define NKT (MD / BKT) // 16 k-tiles
#define BM 32          // rows per block (4 warps x 8 rows)
#define XP 36          // Xs row stride in floats (32 + pad; 144B rows, 16B-aligned)

// Scratch (device globals — no runtime allocation allowed)
__device__ float g_states[2][NB * SEQ * MD];     // ping-pong state buffers
__device__ float g_comp[NB * (SEQ - 1) * MD];    // TreeLSTM [h,c] outputs
__device__ float g_lgpart[NB * (SEQ - 1) * 8];   // selection-logit partials (8 j-chunks)

__device__ __forceinline__ float sig_f(float x) { return 1.0f / (1.0f + __expf(-x)); }
__device__ __forceinline__ float tanh_f(float x) { return 1.0f - 2.0f / (__expf(2.0f * x) + 1.0f); }

// Packed f32x2 helpers (sm_100a; ptxas never auto-fuses these)
__device__ __forceinline__ unsigned long long pack2(float lo, float hi) {
    unsigned long long p;
    asm("mov.b64 %0, {%1, %2};" : "=l"(p) : "f"(lo), "f"(hi));
    return p;
}
__device__ __forceinline__ void unpack2(unsigned long long p, float& lo, float& hi) {
    asm("mov.b64 {%0, %1}, %2;" : "=f"(lo), "=f"(hi) : "l"(p));
}
__device__ __forceinline__ void fma2(unsigned long long& d, unsigned long long a, unsigned long long b) {
    asm("fma.rn.f32x2 %0, %1, %2, %0;" : "+l"(d) : "l"(a), "l"(b));
}
__device__ __forceinline__ void cp_async16(void* smem_dst, const void* gmem_src) {
    unsigned sa = (unsigned)__cvta_generic_to_shared(smem_dst);
    asm volatile("cp.async.cg.shared.global [%0], [%1], 16;" :: "r"(sa), "l"(gmem_src));
}
__device__ __forceinline__ void cp_commit() { asm volatile("cp.async.commit_group;"); }
__device__ __forceinline__ void cp_wait0()  { asm volatile("cp.async.wait_group 0;" ::: "memory"); }

// ---------------------------------------------------------------------------
// Encoder: states0[b][t][:] = embed[sent[b][t]] @ W_enc + b_enc
// ---------------------------------------------------------------------------
__global__ void encode_kernel(const int* __restrict__ sent,
                              const float* __restrict__ emb,
                              const float* __restrict__ W,
                              const float* __restrict__ bias) {
    __shared__ float se[16][WD];
    const int tok0 = blockIdx.x * 16;
    const int tid = threadIdx.x;
    for (int i = tid; i < 16 * WD; i += 256) {
        int t = i / WD, k = i - t * WD;
        se[t][k] = emb[(size_t)sent[tok0 + t] * WD + k];
    }
    __syncthreads();
    const int n = tid;
    float acc[16];
    float bv = bias[n];
#pragma unroll
    for (int t = 0; t < 16; t++) acc[t] = bv;
    for (int k = 0; k < WD; k++) {
        float w = W[k * MD + n];
#pragma unroll
        for (int t = 0; t < 16; t++) acc[t] += se[t][k] * w;
    }
    float* out = g_states[0];
#pragma unroll
    for (int t = 0; t < 16; t++) out[(size_t)(tok0 + t) * MD + n] = acc[t];
}

// ---------------------------------------------------------------------------
// Fused GEMM + TreeLSTM cell + logit partial — K-SPLIT half-warp layout.
// Block: BM=32 rows x 16 gate-cols (jc = blockIdx.y in 0..7) x 5 gates.
// Warp ty owns rows [ty*8, ty*8+8). Lane = (hw, cl): hw = lane>>4 is the
// k-parity, cl = lane&15 is the column j = jc*16+cl. Half-warps process
// adjacent k's, so ONE W LDS.32 serves two k's (k-stride 320B = 16 banks:
// halves hit disjoint banks). Per 2-k warp-step: 20 FFMA2 + 7 crossbar
// phases (ratio 0.35 — under cap) at 3968 warps (high occupancy).
// Epilogue merges k-parity partials with a single shfl_xor(16) per value.
// ---------------------------------------------------------------------------
__global__ __launch_bounds__(128, 5)
void gates_gemm(const float* __restrict__ Wc, const float* __restrict__ bc,
                const float* __restrict__ Wsel, int P, int in) {
    __shared__ float Xs[2][BKT][XP];
    __shared__ float Ws[2][BKT * 80];      // [k][g*16 + cl], 16-col slice, 320B/k

    const float* __restrict__ S = g_states[in];
    const int tid = threadIdx.x;
    const int tx = tid & 31, ty = tid >> 5;
    const int hw = tx >> 4;                // k-parity half
    const int cl = tx & 15;                // column within chunk
    const int jc = blockIdx.y;             // 0..7
    const int j = jc * 16 + cl;            // this lane's gate column
    const int m0 = blockIdx.x * BM;

    // X loader: row mA (0..31), quad kqA (0..3); 128 threads exactly cover tile
    const int mA = tid >> 2;
    const int kqA = tid & 3;
    int roffA;
    {
        int r = m0 + mA;
        int b = r / P;
        roffA = b * (SEQ * MD) + (r - b * P) * MD;
    }

    unsigned long long acc[5][4];
#pragma unroll
    for (int g = 0; g < 5; g++)
#pragma unroll
        for (int rp = 0; rp < 4; rp++) acc[g][rp] = 0ull;

    float4 xr;

    // W prefetch: BKT*80 floats = 320 float4; 128 threads, <=3 each.
    // chunk = I>>2 = k*5+g (0..79), j4 = I&3.
    auto prefW = [&](int kt, int buf) {
        const float* base = Wc + (size_t)kt * 640 + jc * 16;
#pragma unroll
        for (int it = 0; it < 3; it++) {
            int I = it * 128 + tid;
            if (I < 320) {
                int chunk = I >> 2;
                int j4 = I & 3;
                int k = chunk / 5;
                int g = chunk - k * 5;
                cp_async16(&Ws[buf][k * 80 + g * 16 + j4 * 4],
                           base + (size_t)k * 640 + g * 128 + j4 * 4);
            }
        }
    };
    auto ldX = [&](int kt) {
        int kg = kt + kqA * 4;
        int xoff = kg + ((kg >= HF) ? HF : 0);
        xr = *reinterpret_cast<const float4*>(S + roffA + xoff);
    };
    auto stX = [&](int buf) {
        float* xp = &Xs[buf][kqA * 4][mA];
        xp[0 * XP] = xr.x; xp[1 * XP] = xr.y;
        xp[2 * XP] = xr.z; xp[3 * XP] = xr.w;
    };

    // Prologue: tile 0
    prefW(0, 0);
    cp_commit();
    ldX(0);
    stX(0);
    cp_wait0();
    __syncthreads();

    int buf = 0;
    for (int u = 0; u < NKT; u++, buf ^= 1) {
        if (u + 1 < NKT) {
            prefW((u + 1) * BKT, buf ^ 1);
            cp_commit();
            ldX((u + 1) * BKT);
        }
#pragma unroll
        for (int k2 = 0; k2 < BKT; k2 += 2) {
            // lane's k = k2 + hw; halves read disjoint banks (1 phase per LDS)
            const float* wp = &Ws[buf][(k2 + hw) * 80] + cl;
            float w0s = wp[0], w1s = wp[16], w2s = wp[32], w3s = wp[48], w4s = wp[64];
            unsigned long long w0 = pack2(w0s, w0s);
            unsigned long long w1 = pack2(w1s, w1s);
            unsigned long long w2 = pack2(w2s, w2s);
            unsigned long long w3 = pack2(w3s, w3s);
            unsigned long long w4 = pack2(w4s, w4s);
            // X: 8 rows = 4 packed row-pairs for this lane's k (2 x LDS.128)
            const ulonglong2* xpp =
                reinterpret_cast<const ulonglong2*>(&Xs[buf][k2 + hw][ty * 8]);
            ulonglong2 xA = xpp[0];
            ulonglong2 xB = xpp[1];
            fma2(acc[0][0], xA.x, w0); fma2(acc[1][0], xA.x, w1); fma2(acc[2][0], xA.x, w2);
            fma2(acc[3][0], xA.x, w3); fma2(acc[4][0], xA.x, w4);
            fma2(acc[0][1], xA.y, w0); fma2(acc[1][1], xA.y, w1); fma2(acc[2][1], xA.y, w2);
            fma2(acc[3][1], xA.y, w3); fma2(acc[4][1], xA.y, w4);
            fma2(acc[0][2], xB.x, w0); fma2(acc[1][2], xB.x, w1); fma2(acc[2][2], xB.x, w2);
            fma2(acc[3][2], xB.x, w3); fma2(acc[4][2], xB.x, w4);
            fma2(acc[0][3], xB.y, w0); fma2(acc[1][3], xB.y, w1); fma2(acc[2][3], xB.y, w2);
            fma2(acc[3][3], xB.y, w3); fma2(acc[4][3], xB.y, w4);
        }
        if (u + 1 < NKT) stX(buf ^ 1);
        cp_wait0();
        __syncthreads();
    }

    // ---- Merge k-parity partials: lane and lane^16 hold same (rows, col) ----
    float vals[5][8];
#pragma unroll
    for (int g = 0; g < 5; g++)
#pragma unroll
        for (int rp = 0; rp < 4; rp++)
            unpack2(acc[g][rp], vals[g][2 * rp], vals[g][2 * rp + 1]);
#pragma unroll
    for (int g = 0; g < 5; g++)
#pragma unroll
        for (int ri = 0; ri < 8; ri++)
            vals[g][ri] += __shfl_xor_sync(0xFFFFFFFFu, vals[g][ri], 16);

    // Epilogue: bias + TreeLSTM cell + comp write + logit partial.
    // Both halves hold identical sums; only hw==0 stores (avoids dup traffic).
    const float wsh = Wsel[j];
    const float wsc = Wsel[HF + j];
    const float b0 = bc[j];
    const float b1 = bc[128 + j];
    const float b2 = bc[256 + j];
    const float b3 = bc[384 + j];
    const float b4 = bc[512 + j];
#pragma unroll
    for (int ri = 0; ri < 8; ri++) {
        int r = m0 + ty * 8 + ri;
        int b = r / P;
        int roff = b * (SEQ * MD) + (r - b * P) * MD;
        float c_l = S[roff + HF + j];
        float c_r = S[roff + MD + HF + j];
        float c = tanh_f(vals[0][ri] + b0) * sig_f(vals[1][ri] + b1)
                + sig_f(vals[2][ri] + b2) * c_l + sig_f(vals[3][ri] + b3) * c_r;
        float h = sig_f(vals[4][ri] + b4) * tanh_f(c);
        if (hw == 0) {
            float* cp = g_comp + (size_t)r * MD;
            cp[j] = h;
            cp[HF + j] = c;
        }
        float part = h * wsh + c * wsc;
        // reduce over the 16 columns within each half-warp group
#pragma unroll
        for (int o = 8; o > 0; o >>= 1) part += __shfl_xor_sync(0xFFFFFFFFu, part, o);
        if (tx == 0) g_lgpart[r * 8 + jc] = part;
    }
}

// ---------------------------------------------------------------------------
// Per-layer softmax + soft state update. 4 blocks per batch row.
// Softmax done entirely in warp 0 via shfl scan (2 elements/lane, 1 barrier).
// ---------------------------------------------------------------------------
__global__ __launch_bounds__(256)
void update_kernel(int P, int in) {
    __shared__ float prw[64], clw[64], crw[64];
    const int b = blockIdx.x >> 2, q = blockIdx.x & 3;
    const int tid = threadIdx.x;

    if (tid < 32) {
        const int p0 = tid, p1 = tid + 32;
        float l0 = -3.0e38f, l1 = -3.0e38f;
        if (p0 < P) {
            const float4* vp = reinterpret_cast<const float4*>(g_lgpart + (((size_t)b * P + p0) << 3));
            float4 v0 = vp[0], v1 = vp[1];
            l0 = ((v0.x + v0.y) + (v0.z + v0.w)) + ((v1.x + v1.y) + (v1.z + v1.w));
        }
        if (p1 < P) {
            const float4* vp = reinterpret_cast<const float4*>(g_lgpart + (((size_t)b * P + p1) << 3));
            float4 v0 = vp[0], v1 = vp[1];
            l1 = ((v0.x + v0.y) + (v0.z + v0.w)) + ((v1.x + v1.y) + (v1.z + v1.w));
        }
        float m = fmaxf(l0, l1);
#pragma unroll
        for (int o = 16; o > 0; o >>= 1) m = fmaxf(m, __shfl_xor_sync(0xFFFFFFFFu, m, o));
        float e0 = (p0 < P) ? __expf(l0 - m) : 0.f;
        float e1 = (p1 < P) ? __expf(l1 - m) : 0.f;
        // inclusive scan of the 64-slot sequence [e0(lanes 0..31), e1(lanes 0..31)]
        float s0 = e0;
#pragma unroll
        for (int o = 1; o < 32; o <<= 1) {
            float t = __shfl_up_sync(0xFFFFFFFFu, s0, o);
            if (tid >= o) s0 += t;
        }
        float tot0 = __shfl_sync(0xFFFFFFFFu, s0, 31);
        float s1 = e1;
#pragma unroll
        for (int o = 1; o < 32; o <<= 1) {
            float t = __shfl_up_sync(0xFFFFFFFFu, s1, o);
            if (tid >= o) s1 += t;
        }
        s1 += tot0;
        float tot = __shfl_sync(0xFFFFFFFFu, s1, 31);   // padding e==0 -> equals csn[P-1]
        float inv = 1.f / tot;
        prw[p0] = e0 * inv; crw[p0] = (s0 - e0) * inv; clw[p0] = (tot - s0) * inv;
        prw[p1] = e1 * inv; crw[p1] = (s1 - e1) * inv; clw[p1] = (tot - s1) * inv;
    }
    __syncthreads();

    const float* Sb = g_states[in] + b * SEQ * MD;
    float* Ob = g_states[in ^ 1] + b * SEQ * MD;
    const float* Cb = g_comp + (size_t)b * P * MD;
    for (int p = q; p < P; p += 4) {
        Ob[p * MD + tid] = clw[p] * Sb[p * MD + tid]
                         + crw[p] * Sb[(p + 1) * MD + tid]
                         + prw[p] * Cb[p * MD + tid];
    }
}

// ---------------------------------------------------------------------------
// Final MLP: relu(relu(h@W1+b1)@W2+b2)@W_out + b_out. One block per row.
// ---------------------------------------------------------------------------
__global__ void mlp_kernel(const float* __restrict__ W1, const float* __restrict__ b1,
                           const float* __restrict__ W2, const float* __restrict__ b2,
                           const float* __restrict__ Wo, const float* __restrict__ bo,
                           float* __restrict__ out, int in) {
    const int b = blockIdx.x, tid = threadIdx.x;
    __shared__ float h0[MD];
    __shared__ float h1[MLPD];
    __shared__ float h2[MLPD];
    __shared__ float red[256];
    const float* S = g_states[in] + (size_t)b * SEQ * MD;
    for (int i = tid; i < MD; i += 256) h0[i] = S[i];
    __syncthreads();
#pragma unroll
    for (int ni = 0; ni < MLPD / 256; ni++) {
        int n = tid + ni * 256;
        float acc = b1[n];
        for (int k = 0; k < MD; k++) acc += h0[k] * W1[(size_t)k * MLPD + n];
        h1[n] = fmaxf(acc, 0.f);
    }
    __syncthreads();
#pragma unroll
    for (int ni = 0; ni < MLPD / 256; ni++) {
        int n = tid + ni * 256;
        float acc = b2[n];
        for (int k = 0; k < MLPD; k++) acc += h1[k] * W2[(size_t)k * MLPD + n];
        h2[n] = fmaxf(acc, 0.f);
    }
    __syncthreads();
    for (int c = 0; c < NC; c++) {
        float part = 0.f;
        for (int k = tid; k < MLPD; k += 256) part += h2[k] * Wo[(size_t)k * NC + c];
        red[tid] = part;
        __syncthreads();
        for (int s = 128; s > 0; s >>= 1) {
            if (tid < s) red[tid] += red[tid + s];
            __syncthreads();
        }
        if (tid == 0) out[b * NC + c] = red[0] + bo[c];
        __syncthreads();
    }
}

// ---------------------------------------------------------------------------
extern "C" void kernel_launch(void* const* d_in, const int* in_sizes, int n_in,
                              void* d_out, int out_size) {
    const int*   sent   = (const int*)  d_in[0];
    const float* emb    = (const float*)d_in[1];
    const float* W_enc  = (const float*)d_in[2];
    const float* b_enc  = (const float*)d_in[3];
    const float* W_comp = (const float*)d_in[4];
    const float* b_comp = (const float*)d_in[5];
    const float* W_sel  = (const float*)d_in[6];
    // d_in[7] = b_sel (constant shift, softmax-invariant — not needed)
    const float* W1     = (const float*)d_in[8];
    const float* b1     = (const float*)d_in[9];
    const float* W2     = (const float*)d_in[10];
    const float* b2     = (const float*)d_in[11];
    const float* Wo     = (const float*)d_in[12];
    const float* bo     = (const float*)d_in[13];
    float* out = (float*)d_out;

    encode_kernel<<<NB * SEQ / 16, 256>>>(sent, emb, W_enc, b_enc);

    int cur = 0;
    for (int P = SEQ - 1; P >= 1; --P) {
        dim3 grid(NB * P / BM, 8);       // 64P always divisible by 32; 8 col-chunks
        gates_gemm<<<grid, 128>>>(W_comp, b_comp, W_sel, P, cur);
        update_kernel<<<NB * 4, 256>>>(P, cur);
        cur ^= 1;
    }

    mlp_kernel<<<NB, 256>>>(W1, b1, W2, b2, Wo, bo, out, 1);  // 63 layers -> parity 1
}